// round 6
// baseline (speedup 1.0000x reference)
#include <cuda_runtime.h>
#include <cstdint>

// HashEmbedding: B*L=819200 tokens, H=2, E=64, out=[emb(64), pv0, pv1] f32
// d_in: words int32[819200], hash_table int32[1000000,2],
//       W f32[100000,64], P f32[1000000,2]

static constexpr int NTOK  = 16384 * 50;   // 819200
static constexpr int EMBED = 64;
static constexpr int OUTW  = EMBED + 2;    // 66
static constexpr int TPW   = 32;           // tokens per warp (lane t owns token t's scalars)
static constexpr int TPB   = 256;

__global__ void __launch_bounds__(TPB)
hash_embedding_kernel(const int*    __restrict__ words,
                      const int2*   __restrict__ hash_table,
                      const float*  __restrict__ W,
                      const float2* __restrict__ P2,
                      float*        __restrict__ out)
{
    const int warp = (blockIdx.x * blockDim.x + threadIdx.x) >> 5;
    const int lane = threadIdx.x & 31;
    const int base = warp * TPW;
    if (base >= NTOK) return;
    const float* Pf = reinterpret_cast<const float*>(P2);

    // ---- Scalar phase: lane t owns token base+t. 4 load instructions total
    // cover all 32 tokens' words, hashes, weights, pvals. ----
    const int    w   = __ldg(&words[base + lane]);        // fully coalesced (128B)
    const int2   h   = __ldg(&hash_table[w]);             // 8B gather
    const float2 pwv = __ldg(&P2[w]);                     // 8B gather

    float2 pv;
    pv.x = __ldg(&Pf[(size_t)h.x * 2 + 0]);
    pv.y = __ldg(&Pf[(size_t)h.y * 2 + 1]);
    // pvals out: one scattered float2 store covers all 32 tokens' cols 64..65
    *reinterpret_cast<float2*>(out + (size_t)(base + lane) * OUTW + EMBED) = pv;

    // ---- Streaming phase: broadcast token t's scalars from lane t, gather
    // its two W rows (8B/lane, coalesced 256B), combine, store. unroll 8
    // keeps 16 W-row gathers in flight per warp continuously. ----
#pragma unroll 8
    for (int t = 0; t < TPW; t++) {
        const int   hx = __shfl_sync(0xffffffffu, h.x,   t);
        const int   hy = __shfl_sync(0xffffffffu, h.y,   t);
        const float px = __shfl_sync(0xffffffffu, pwv.x, t);
        const float py = __shfl_sync(0xffffffffu, pwv.y, t);

        const float2 a = __ldg(reinterpret_cast<const float2*>(W + (size_t)hx * EMBED) + lane);
        const float2 b = __ldg(reinterpret_cast<const float2*>(W + (size_t)hy * EMBED) + lane);

        float2 e;
        e.x = fmaf(a.x, px, b.x * py);
        e.y = fmaf(a.y, px, b.y * py);

        float* o = out + (size_t)(base + t) * OUTW;   // 264B stride, 8B aligned
        reinterpret_cast<float2*>(o)[lane] = e;       // cols 0..63
    }
}

extern "C" void kernel_launch(void* const* d_in, const int* in_sizes, int n_in,
                              void* d_out, int out_size)
{
    const int*    words      = (const int*)d_in[0];
    const int2*   hash_table = (const int2*)d_in[1];
    const float*  W          = (const float*)d_in[2];
    const float2* P          = (const float2*)d_in[3];
    float*        out        = (float*)d_out;

    const int tokens_per_block = (TPB / 32) * TPW;                       // 256
    const int blocks = (NTOK + tokens_per_block - 1) / tokens_per_block; // 3200
    hash_embedding_kernel<<<blocks, TPB>>>(words, hash_table, W, P, out);
}

// round 7
// speedup vs baseline: 1.4590x; 1.4590x over previous
#include <cuda_runtime.h>
#include <cstdint>

// HashEmbedding: B*L=819200 tokens, H=2, E=64, out=[emb(64), pv0, pv1] f32
// d_in: words int32[819200], hash_table int32[1000000,2],
//       W f32[100000,64], P f32[1000000,2]

static constexpr int NTOK  = 16384 * 50;   // 819200
static constexpr int EMBED = 64;
static constexpr int OUTW  = EMBED + 2;    // 66
static constexpr int TPW   = 8;            // tokens per warp
static constexpr int TPB   = 256;

__global__ void __launch_bounds__(TPB)
hash_embedding_kernel(const int*    __restrict__ words,
                      const int2*   __restrict__ hash_table,
                      const float*  __restrict__ W,
                      const float2* __restrict__ P2,
                      float*        __restrict__ out)
{
    const int warp = (blockIdx.x * blockDim.x + threadIdx.x) >> 5;
    const int lane = threadIdx.x & 31;
    const int base = warp * TPW;
    if (base >= NTOK) return;
    const float* Pf = reinterpret_cast<const float*>(P2);

    // ---- Distributed scalar phase: lane t (mod 8) owns token base+t.
    // Lanes 8-31 replicate lanes 0-7's addresses: in-warp dedup means no
    // extra sectors/wavefronts, and no divergence. One LDG per stage
    // covers all 8 tokens (vs 8 broadcast LDGs). ----
    const int    tok = base + (lane & 7);
    const int    w   = __ldg(&words[tok]);
    const int2   h   = __ldg(&hash_table[w]);
    const float2 pwv = __ldg(&P2[w]);

    // pvals: gather + store only on owning lanes (avoid duplicate stores)
    if (lane < TPW) {
        float2 pv;
        pv.x = __ldg(&Pf[(size_t)h.x * 2 + 0]);
        pv.y = __ldg(&Pf[(size_t)h.y * 2 + 1]);
        *reinterpret_cast<float2*>(out + (size_t)tok * OUTW + EMBED) = pv;
    }

    // ---- Burst-issue all 16 W-row gathers (8B/lane, coalesced 256B rows).
    // Scalars come off lane t via SHFL (ALU pipe) instead of LSU broadcasts. ----
    float2 a[TPW], b[TPW];
#pragma unroll
    for (int t = 0; t < TPW; t++) {
        const int hx = __shfl_sync(0xffffffffu, h.x, t);
        const int hy = __shfl_sync(0xffffffffu, h.y, t);
        a[t] = __ldg(reinterpret_cast<const float2*>(W + (size_t)hx * EMBED) + lane);
        b[t] = __ldg(reinterpret_cast<const float2*>(W + (size_t)hy * EMBED) + lane);
    }

    // ---- Consume in order (frees a[t]/b[t] early), store. ----
#pragma unroll
    for (int t = 0; t < TPW; t++) {
        const float px = __shfl_sync(0xffffffffu, pwv.x, t);
        const float py = __shfl_sync(0xffffffffu, pwv.y, t);
        float2 e;
        e.x = fmaf(a[t].x, px, b[t].x * py);
        e.y = fmaf(a[t].y, px, b[t].y * py);
        float* o = out + (size_t)(base + t) * OUTW;   // 264B stride, 8B aligned
        reinterpret_cast<float2*>(o)[lane] = e;       // cols 0..63
    }
}

extern "C" void kernel_launch(void* const* d_in, const int* in_sizes, int n_in,
                              void* d_out, int out_size)
{
    const int*    words      = (const int*)d_in[0];
    const int2*   hash_table = (const int2*)d_in[1];
    const float*  W          = (const float*)d_in[2];
    const float2* P          = (const float2*)d_in[3];
    float*        out        = (float*)d_out;

    const int tokens_per_block = (TPB / 32) * TPW;                        // 64
    const int blocks = (NTOK + tokens_per_block - 1) / tokens_per_block;  // 12800
    hash_embedding_kernel<<<blocks, TPB>>>(words, hash_table, W, P, out);
}